// round 16
// baseline (speedup 1.0000x reference)
#include <cuda_runtime.h>
#include <cstdint>

// out = X @ TT(g0,g1,g2) + bias, structured (all fp32 exact, FFMA2 inner loops):
//   Stage1: A[n][k*64+a]   = sum_ij X[n][ij*16+k] * g0[ij][a]
//   Stage2: B[n][l*64+b]   = sum_{kk} A[n][kk] * W1[kk][l*64+b]   (1024x1024 SGEMM)
//   Stage3: out[n][l*256+mn] = sum_b B[n][l*64+b] * g2[b][mn] + bias
// No tcgen05 (PTX target is compute_103; 'a'-features unavailable).

typedef unsigned long long u64;

__device__ float g_A[(size_t)8192 * 1024];          // [m][kk], row-major
__device__ float g_B[(size_t)8192 * 1024];          // [m][n]
__device__ float g_Wd[(size_t)1024 * 4 * 128 * 4];  // W dup-pair chunks (8MB)
// g_Wd layout: 16B unit index u = (kk*4 + c)*128 + nx holds
//   { W[kk][nx*8+2c], dup, W[kk][nx*8+2c+1], dup }

__device__ __forceinline__ u64 pk2(float x, float y) {
    u64 r; asm("mov.b64 %0, {%1, %2};" : "=l"(r) : "f"(x), "f"(y)); return r;
}
__device__ __forceinline__ void fma2(u64 &d, u64 a, u64 b) {
    asm("fma.rn.f32x2 %0, %1, %2, %0;" : "+l"(d) : "l"(a), "l"(b));
}

// ---------------------------------------------------------------------------
// Reorder: g1[a][k][l][b] -> g_Wd dup-pair chunked, W1[kk=k*64+a][n=l*64+b]
// ---------------------------------------------------------------------------
__global__ void k_reorder(const float* __restrict__ g1) {
    int idx = blockIdx.x * 256 + threadIdx.x;   // 0 .. 1024*512-1 (pair index)
    int np = idx & 511, kk = idx >> 9;
    int n = np * 2, l = n >> 6, b = n & 63;
    int k = kk >> 6, a = kk & 63;
    float2 v = *(const float2*)&g1[(((a * 16 + k) * 16 + l) * 64) + b];
    int nx = np >> 2, c = np & 3;
    *(float4*)&g_Wd[(size_t)(((kk * 4 + c) * 128) + nx) * 4] =
        make_float4(v.x, v.x, v.y, v.y);
}

// ---------------------------------------------------------------------------
// Stage 1: 4 rows / block, row-pair packed x, dup-chunked g0.
// thread -> (k = tid>>4, ag = tid&15; a = ag*4+q, q=0..3)
// ---------------------------------------------------------------------------
__global__ __launch_bounds__(256) void k_stage1(const float* __restrict__ X,
                                                const float* __restrict__ g0) {
    __shared__ float Xs[4][512];
    __shared__ float M0d[32][2][16][4];   // [u][c][ag][dup-pair 16B]
    int tid  = threadIdx.x;
    int row0 = blockIdx.x * 4;
    int k = tid >> 4, ag = tid & 15;

    u64 acc[4][2] = {};                   // [q][row-pair]

    for (int ch = 0; ch < 8; ch++) {      // 8 chunks of 32 ij
        __syncthreads();
        #pragma unroll
        for (int i = 0; i < 2; i++) {     // Xs: 4 rows x 512 cols
            int t = tid + i * 256;
            int r = t >> 7, cc = (t & 127) * 4;
            *(float4*)&Xs[r][cc] =
                *(const float4*)&X[(size_t)(row0 + r) * 4096 + ch * 512 + cc];
        }
        #pragma unroll
        for (int i = 0; i < 4; i++) {     // M0d: 32 u x 32 dup-pairs
            int t = tid + i * 256;
            int u = t >> 5, pp = t & 31, c = pp >> 4, agf = pp & 15;
            float2 v = *(const float2*)&g0[(ch * 32 + u) * 64 + agf * 4 + c * 2];
            *(float4*)&M0d[u][c][agf][0] = make_float4(v.x, v.x, v.y, v.y);
        }
        __syncthreads();
        #pragma unroll
        for (int u = 0; u < 32; u++) {
            ulonglong2 w0 = *(ulonglong2*)&M0d[u][0][ag][0];  // q=0,1 dup pairs
            ulonglong2 w1 = *(ulonglong2*)&M0d[u][1][ag][0];  // q=2,3
            int xc = u * 16 + k;
            u64 xp0 = pk2(Xs[0][xc], Xs[1][xc]);
            u64 xp1 = pk2(Xs[2][xc], Xs[3][xc]);
            fma2(acc[0][0], xp0, w0.x);  fma2(acc[0][1], xp1, w0.x);
            fma2(acc[1][0], xp0, w0.y);  fma2(acc[1][1], xp1, w0.y);
            fma2(acc[2][0], xp0, w1.x);  fma2(acc[2][1], xp1, w1.x);
            fma2(acc[3][0], xp0, w1.y);  fma2(acc[3][1], xp1, w1.y);
        }
    }
    #pragma unroll
    for (int r = 0; r < 4; r++) {
        float4 v;
        float* f = (float*)&v;
        #pragma unroll
        for (int q = 0; q < 4; q++) {
            float2 p = *(float2*)&acc[q][r >> 1];
            f[q] = (r & 1) ? p.y : p.x;
        }
        *(float4*)&g_A[(size_t)(row0 + r) * 1024 + k * 64 + ag * 4] = v;
    }
}

// ---------------------------------------------------------------------------
// Stage 2: SGEMM 8192x1024x1024, pk2-free FFMA2.
// CTA 128x128 tile, K-tile 16, double-buffered smem, 1 sync/kt.
// A in smem k-major (row-pairs via broadcast LDS), W dup-chunked (LDS.128 cf).
// Per k: 6 LDS.128 + 32 FFMA2.
// ---------------------------------------------------------------------------
__global__ __launch_bounds__(256) void k_stage2() {
    __shared__ float Asm[2][16][128];          // [buf][k][m]        8KB x2
    __shared__ float Wd[2][16][4][16][4];      // [buf][k][c][tx][4] 16KB x2
    int tid = threadIdx.x;
    int m0 = blockIdx.y * 128, n0 = blockIdx.x * 128;
    int ty = tid >> 4, tx = tid & 15;
    int arow = tid & 127, kq8 = (tid >> 7) * 8;
    int nx0 = n0 >> 3;

    float4 pa0, pa1; uint4 pw[4];
    auto LOADG = [&](int kt) {
        const float* ap = &g_A[(size_t)(m0 + arow) * 1024 + kt * 16 + kq8];
        pa0 = *(const float4*)ap;
        pa1 = *(const float4*)(ap + 4);
        #pragma unroll
        for (int c = 0; c < 4; c++)
            pw[c] = *(const uint4*)&g_Wd[(size_t)((((kt * 16 + ty) * 4) + c) * 128
                                                  + nx0 + tx) * 4];
    };
    auto STORES = [&](int buf) {
        #pragma unroll
        for (int i = 0; i < 4; i++) {
            Asm[buf][kq8 + i][arow]     = ((float*)&pa0)[i];
            Asm[buf][kq8 + 4 + i][arow] = ((float*)&pa1)[i];
        }
        #pragma unroll
        for (int c = 0; c < 4; c++)
            *(uint4*)&Wd[buf][ty][c][tx][0] = pw[c];
    };

    u64 acc[4][8] = {};                        // [row-pair][col]

    LOADG(0); STORES(0); __syncthreads();
    for (int kt = 0; kt < 64; kt++) {
        int buf = kt & 1;
        if (kt < 63) LOADG(kt + 1);
        #pragma unroll
        for (int k = 0; k < 16; k++) {
            ulonglong2 a01 = *(ulonglong2*)&Asm[buf][k][ty * 8];
            ulonglong2 a23 = *(ulonglong2*)&Asm[buf][k][ty * 8 + 4];
            u64 ap[4] = {a01.x, a01.y, a23.x, a23.y};
            ulonglong2 wc0 = *(ulonglong2*)&Wd[buf][k][0][tx][0];
            ulonglong2 wc1 = *(ulonglong2*)&Wd[buf][k][1][tx][0];
            ulonglong2 wc2 = *(ulonglong2*)&Wd[buf][k][2][tx][0];
            ulonglong2 wc3 = *(ulonglong2*)&Wd[buf][k][3][tx][0];
            u64 w[8] = {wc0.x, wc0.y, wc1.x, wc1.y, wc2.x, wc2.y, wc3.x, wc3.y};
            #pragma unroll
            for (int ip = 0; ip < 4; ip++)
                #pragma unroll
                for (int j = 0; j < 8; j++)
                    fma2(acc[ip][j], ap[ip], w[j]);
        }
        if (kt < 63) { STORES(buf ^ 1); __syncthreads(); }
    }

    #pragma unroll
    for (int r = 0; r < 8; r++) {
        float4 v0, v1;
        #pragma unroll
        for (int j = 0; j < 8; j++) {
            float2 p = *(float2*)&acc[r >> 1][j];
            float f = (r & 1) ? p.y : p.x;
            if (j < 4) ((float*)&v0)[j] = f; else ((float*)&v1)[j - 4] = f;
        }
        float* dst = &g_B[(size_t)(m0 + ty * 8 + r) * 1024 + n0 + tx * 8];
        *(float4*)dst = v0;
        *(float4*)(dst + 4) = v1;
    }
}

// ---------------------------------------------------------------------------
// Stage 3: pk2-free. Per block: 64 rows x 256 cols for one l.
// W2 pre-duplicated in shared (LDS.64 cf); acc packs row pairs (B broadcast).
// ---------------------------------------------------------------------------
__global__ __launch_bounds__(256) void k_stage3(const float* __restrict__ g2,
                                                const float* __restrict__ bias,
                                                float* __restrict__ out) {
    __shared__ float W2d[16][512];   // duplicated cols
    __shared__ float Bt[16][72];     // [k][row], padded
    int tid  = threadIdx.x;
    int n0   = blockIdx.x * 64;
    int l    = blockIdx.y;
    int ty   = tid >> 5;
    int lane = tid & 31;

    u64 acc[4][8] = {};              // [row-pair][col j]

    for (int kc = 0; kc < 4; kc++) {
        __syncthreads();
        #pragma unroll
        for (int i = 0; i < 16; i++) {
            float v = g2[(kc * 16 + i) * 256 + tid];
            *(float2*)&W2d[i][2 * tid] = make_float2(v, v);
        }
        {
            int r = tid >> 2, c0 = (tid & 3) * 4;
            float4 v = *(const float4*)&g_B[(size_t)(n0 + r) * 1024
                                            + l * 64 + kc * 16 + c0];
            Bt[c0 + 0][r] = v.x; Bt[c0 + 1][r] = v.y;
            Bt[c0 + 2][r] = v.z; Bt[c0 + 3][r] = v.w;
        }
        __syncthreads();
        #pragma unroll
        for (int k = 0; k < 16; k++) {
            u64 w[8];
            #pragma unroll
            for (int j = 0; j < 8; j++)
                w[j] = *(const u64*)&W2d[k][2 * (lane + 32 * j)];
            #pragma unroll
            for (int p = 0; p < 4; p++) {
                u64 bp = *(const u64*)&Bt[k][ty * 8 + 2 * p];   // broadcast
                #pragma unroll
                for (int j = 0; j < 8; j++)
                    fma2(acc[p][j], bp, w[j]);
            }
        }
    }

    #pragma unroll
    for (int j = 0; j < 8; j++) {
        int col = l * 256 + lane + 32 * j;
        float bb = __ldg(&bias[col]);
        #pragma unroll
        for (int p = 0; p < 4; p++) {
            float2 v = *(float2*)&acc[p][j];
            out[(size_t)(n0 + ty * 8 + 2 * p) * 4096 + col]     = v.x + bb;
            out[(size_t)(n0 + ty * 8 + 2 * p + 1) * 4096 + col] = v.y + bb;
        }
    }
}

// ---------------------------------------------------------------------------
extern "C" void kernel_launch(void* const* d_in, const int* in_sizes, int n_in,
                              void* d_out, int out_size) {
    const float* x    = (const float*)d_in[0];   // (4,2048,4096)
    const float* g0   = (const float*)d_in[1];   // (1,16,16,64)
    const float* g1   = (const float*)d_in[2];   // (64,16,16,64)
    const float* g2   = (const float*)d_in[3];   // (64,16,16,1)
    const float* bias = (const float*)d_in[4];   // (4096,)
    float* out = (float*)d_out;                  // (8192,4096)

    k_reorder<<<2048, 256>>>(g1);
    k_stage1 <<<2048, 256>>>(x, g0);
    k_stage2 <<<dim3(8, 64), 256>>>();
    k_stage3 <<<dim3(128, 16), 256>>>(g2, bias, out);
}

// round 17
// speedup vs baseline: 1.0036x; 1.0036x over previous
#include <cuda_runtime.h>
#include <cstdint>

// out = X @ TT(g0,g1,g2) + bias, structured (all fp32 exact, FFMA2 inner loops):
//   Stage1: A[n][k*64+a]   = sum_ij X[n][ij*16+k] * g0[ij][a]
//   Stage2: B[n][l*64+b]   = sum_{kk} A[n][kk] * W1[kk][l*64+b]   (1024x1024 SGEMM)
//   Stage3: out[n][l*256+mn] = sum_b B[n][l*64+b] * g2[b][mn] + bias
// No tcgen05 (PTX target is compute_103; 'a'-features unavailable).

typedef unsigned long long u64;

__device__ float g_A[(size_t)8192 * 1024];          // [m][kk], row-major
__device__ float g_B[(size_t)8192 * 1024];          // [m][n]
__device__ float g_Wd[(size_t)1024 * 4 * 128 * 4];  // W dup-pair chunks (8MB)
// g_Wd layout: 16B unit index u = (kk*4 + c)*128 + nx holds
//   { W[kk][nx*8+2c], dup, W[kk][nx*8+2c+1], dup }

__device__ __forceinline__ u64 pk2(float x, float y) {
    u64 r; asm("mov.b64 %0, {%1, %2};" : "=l"(r) : "f"(x), "f"(y)); return r;
}
__device__ __forceinline__ void fma2(u64 &d, u64 a, u64 b) {
    asm("fma.rn.f32x2 %0, %1, %2, %0;" : "+l"(d) : "l"(a), "l"(b));
}

// ---------------------------------------------------------------------------
// Reorder: g1[a][k][l][b] -> g_Wd dup-pair chunked, W1[kk=k*64+a][n=l*64+b]
// ---------------------------------------------------------------------------
__global__ void k_reorder(const float* __restrict__ g1) {
    int idx = blockIdx.x * 256 + threadIdx.x;   // 0 .. 1024*512-1 (pair index)
    int np = idx & 511, kk = idx >> 9;
    int n = np * 2, l = n >> 6, b = n & 63;
    int k = kk >> 6, a = kk & 63;
    float2 v = *(const float2*)&g1[(((a * 16 + k) * 16 + l) * 64) + b];
    int nx = np >> 2, c = np & 3;
    *(float4*)&g_Wd[(size_t)(((kk * 4 + c) * 128) + nx) * 4] =
        make_float4(v.x, v.x, v.y, v.y);
}

// ---------------------------------------------------------------------------
// Stage 1: 4 rows / block, row-pair packed x, dup-chunked g0.
// thread -> (k = tid>>4, ag = tid&15; a = ag*4+q, q=0..3)
// ---------------------------------------------------------------------------
__global__ __launch_bounds__(256) void k_stage1(const float* __restrict__ X,
                                                const float* __restrict__ g0) {
    __shared__ float Xs[4][512];
    __shared__ float M0d[32][2][16][4];   // [u][c][ag][dup-pair 16B]
    int tid  = threadIdx.x;
    int row0 = blockIdx.x * 4;
    int k = tid >> 4, ag = tid & 15;

    u64 acc[4][2] = {};                   // [q][row-pair]

    for (int ch = 0; ch < 8; ch++) {      // 8 chunks of 32 ij
        __syncthreads();
        #pragma unroll
        for (int i = 0; i < 2; i++) {     // Xs: 4 rows x 512 cols
            int t = tid + i * 256;
            int r = t >> 7, cc = (t & 127) * 4;
            *(float4*)&Xs[r][cc] =
                *(const float4*)&X[(size_t)(row0 + r) * 4096 + ch * 512 + cc];
        }
        #pragma unroll
        for (int i = 0; i < 4; i++) {     // M0d: 32 u x 32 dup-pairs
            int t = tid + i * 256;
            int u = t >> 5, pp = t & 31, c = pp >> 4, agf = pp & 15;
            float2 v = *(const float2*)&g0[(ch * 32 + u) * 64 + agf * 4 + c * 2];
            *(float4*)&M0d[u][c][agf][0] = make_float4(v.x, v.x, v.y, v.y);
        }
        __syncthreads();
        #pragma unroll
        for (int u = 0; u < 32; u++) {
            ulonglong2 w0 = *(ulonglong2*)&M0d[u][0][ag][0];  // q=0,1 dup pairs
            ulonglong2 w1 = *(ulonglong2*)&M0d[u][1][ag][0];  // q=2,3
            int xc = u * 16 + k;
            u64 xp0 = pk2(Xs[0][xc], Xs[1][xc]);
            u64 xp1 = pk2(Xs[2][xc], Xs[3][xc]);
            fma2(acc[0][0], xp0, w0.x);  fma2(acc[0][1], xp1, w0.x);
            fma2(acc[1][0], xp0, w0.y);  fma2(acc[1][1], xp1, w0.y);
            fma2(acc[2][0], xp0, w1.x);  fma2(acc[2][1], xp1, w1.x);
            fma2(acc[3][0], xp0, w1.y);  fma2(acc[3][1], xp1, w1.y);
        }
    }
    #pragma unroll
    for (int r = 0; r < 4; r++) {
        float4 v;
        float* f = (float*)&v;
        #pragma unroll
        for (int q = 0; q < 4; q++) {
            float2 p = *(float2*)&acc[q][r >> 1];
            f[q] = (r & 1) ? p.y : p.x;
        }
        *(float4*)&g_A[(size_t)(row0 + r) * 1024 + k * 64 + ag * 4] = v;
    }
}

// ---------------------------------------------------------------------------
// Stage 2: SGEMM 8192x1024x1024, pk2-free FFMA2.
// CTA 128x128 tile, K-tile 16, double-buffered smem, 1 sync/kt.
// A in smem k-major (row-pairs via broadcast LDS), W dup-chunked (LDS.128 cf).
// Per k: 6 LDS.128 + 32 FFMA2.
// ---------------------------------------------------------------------------
__global__ __launch_bounds__(256) void k_stage2() {
    __shared__ float Asm[2][16][128];          // [buf][k][m]        8KB x2
    __shared__ float Wd[2][16][4][16][4];      // [buf][k][c][tx][4] 16KB x2
    int tid = threadIdx.x;
    int m0 = blockIdx.y * 128, n0 = blockIdx.x * 128;
    int ty = tid >> 4, tx = tid & 15;
    int arow = tid & 127, kq8 = (tid >> 7) * 8;
    int nx0 = n0 >> 3;

    float4 pa0, pa1; uint4 pw[4];
    auto LOADG = [&](int kt) {
        const float* ap = &g_A[(size_t)(m0 + arow) * 1024 + kt * 16 + kq8];
        pa0 = *(const float4*)ap;
        pa1 = *(const float4*)(ap + 4);
        #pragma unroll
        for (int c = 0; c < 4; c++)
            pw[c] = *(const uint4*)&g_Wd[(size_t)((((kt * 16 + ty) * 4) + c) * 128
                                                  + nx0 + tx) * 4];
    };
    auto STORES = [&](int buf) {
        #pragma unroll
        for (int i = 0; i < 4; i++) {
            Asm[buf][kq8 + i][arow]     = ((float*)&pa0)[i];
            Asm[buf][kq8 + 4 + i][arow] = ((float*)&pa1)[i];
        }
        #pragma unroll
        for (int c = 0; c < 4; c++)
            *(uint4*)&Wd[buf][ty][c][tx][0] = pw[c];
    };

    u64 acc[4][8] = {};                        // [row-pair][col]

    LOADG(0); STORES(0); __syncthreads();
    for (int kt = 0; kt < 64; kt++) {
        int buf = kt & 1;
        if (kt < 63) LOADG(kt + 1);
        #pragma unroll
        for (int k = 0; k < 16; k++) {
            ulonglong2 a01 = *(ulonglong2*)&Asm[buf][k][ty * 8];
            ulonglong2 a23 = *(ulonglong2*)&Asm[buf][k][ty * 8 + 4];
            u64 ap[4] = {a01.x, a01.y, a23.x, a23.y};
            ulonglong2 wc0 = *(ulonglong2*)&Wd[buf][k][0][tx][0];
            ulonglong2 wc1 = *(ulonglong2*)&Wd[buf][k][1][tx][0];
            ulonglong2 wc2 = *(ulonglong2*)&Wd[buf][k][2][tx][0];
            ulonglong2 wc3 = *(ulonglong2*)&Wd[buf][k][3][tx][0];
            u64 w[8] = {wc0.x, wc0.y, wc1.x, wc1.y, wc2.x, wc2.y, wc3.x, wc3.y};
            #pragma unroll
            for (int ip = 0; ip < 4; ip++)
                #pragma unroll
                for (int j = 0; j < 8; j++)
                    fma2(acc[ip][j], ap[ip], w[j]);
        }
        if (kt < 63) { STORES(buf ^ 1); __syncthreads(); }
    }

    #pragma unroll
    for (int r = 0; r < 8; r++) {
        float4 v0, v1;
        #pragma unroll
        for (int j = 0; j < 8; j++) {
            float2 p = *(float2*)&acc[r >> 1][j];
            float f = (r & 1) ? p.y : p.x;
            if (j < 4) ((float*)&v0)[j] = f; else ((float*)&v1)[j - 4] = f;
        }
        float* dst = &g_B[(size_t)(m0 + ty * 8 + r) * 1024 + n0 + tx * 8];
        *(float4*)dst = v0;
        *(float4*)(dst + 4) = v1;
    }
}

// ---------------------------------------------------------------------------
// Stage 3: pk2-free. Per block: 64 rows x 256 cols for one l.
// W2 pre-duplicated in shared (LDS.64 cf); acc packs row pairs (B broadcast).
// ---------------------------------------------------------------------------
__global__ __launch_bounds__(256) void k_stage3(const float* __restrict__ g2,
                                                const float* __restrict__ bias,
                                                float* __restrict__ out) {
    __shared__ float W2d[16][512];   // duplicated cols
    __shared__ float Bt[16][72];     // [k][row], padded
    int tid  = threadIdx.x;
    int n0   = blockIdx.x * 64;
    int l    = blockIdx.y;
    int ty   = tid >> 5;
    int lane = tid & 31;

    u64 acc[4][8] = {};              // [row-pair][col j]

    for (int kc = 0; kc < 4; kc++) {
        __syncthreads();
        #pragma unroll
        for (int i = 0; i < 16; i++) {
            float v = g2[(kc * 16 + i) * 256 + tid];
            *(float2*)&W2d[i][2 * tid] = make_float2(v, v);
        }
        {
            int r = tid >> 2, c0 = (tid & 3) * 4;
            float4 v = *(const float4*)&g_B[(size_t)(n0 + r) * 1024
                                            + l * 64 + kc * 16 + c0];
            Bt[c0 + 0][r] = v.x; Bt[c0 + 1][r] = v.y;
            Bt[c0 + 2][r] = v.z; Bt[c0 + 3][r] = v.w;
        }
        __syncthreads();
        #pragma unroll
        for (int k = 0; k < 16; k++) {
            u64 w[8];
            #pragma unroll
            for (int j = 0; j < 8; j++)
                w[j] = *(const u64*)&W2d[k][2 * (lane + 32 * j)];
            #pragma unroll
            for (int p = 0; p < 4; p++) {
                u64 bp = *(const u64*)&Bt[k][ty * 8 + 2 * p];   // broadcast
                #pragma unroll
                for (int j = 0; j < 8; j++)
                    fma2(acc[p][j], bp, w[j]);
            }
        }
    }

    #pragma unroll
    for (int j = 0; j < 8; j++) {
        int col = l * 256 + lane + 32 * j;
        float bb = __ldg(&bias[col]);
        #pragma unroll
        for (int p = 0; p < 4; p++) {
            float2 v = *(float2*)&acc[p][j];
            out[(size_t)(n0 + ty * 8 + 2 * p) * 4096 + col]     = v.x + bb;
            out[(size_t)(n0 + ty * 8 + 2 * p + 1) * 4096 + col] = v.y + bb;
        }
    }
}

// ---------------------------------------------------------------------------
extern "C" void kernel_launch(void* const* d_in, const int* in_sizes, int n_in,
                              void* d_out, int out_size) {
    const float* x    = (const float*)d_in[0];   // (4,2048,4096)
    const float* g0   = (const float*)d_in[1];   // (1,16,16,64)
    const float* g1   = (const float*)d_in[2];   // (64,16,16,64)
    const float* g2   = (const float*)d_in[3];   // (64,16,16,1)
    const float* bias = (const float*)d_in[4];   // (4096,)
    float* out = (float*)d_out;                  // (8192,4096)

    k_reorder<<<2048, 256>>>(g1);
    k_stage1 <<<2048, 256>>>(x, g0);
    k_stage2 <<<dim3(8, 64), 256>>>();
    k_stage3 <<<dim3(128, 16), 256>>>(g2, bias, out);
}